// round 1
// baseline (speedup 1.0000x reference)
#include <cuda_runtime.h>
#include <math.h>

#define NUMS  128
#define BATCH 256
#define HCH   64
#define DIM   32
#define HID   256
#define XDIM  65   // 1 + HCH
#define KW    32
#define DT    (1.0f/128.0f)

// ---------------- device scratch (no allocation allowed) ----------------
__device__ float d_gvals[NUMS + 1];
__device__ float d_kmu[NUMS + 1];
__device__ float d_ksig[NUMS + 1];
__device__ float d_H[BATCH * 2 * HID];          // [b][0:256)=mu hidden, [256:512)=sig hidden
__device__ float d_muh[NUMS * BATCH * HCH];     // mu history, j=0..127
__device__ float d_svh[NUMS * BATCH * HCH];     // sv history, j=0..127

// ---------------- init: tiny kernel MLPs g/kmu/ksig over t grid ----------------
__global__ void init_kernel(const float* gw1, const float* gb1, const float* gw2, const float* gb2,
                            const float* mw1, const float* mb1, const float* mw2, const float* mb2,
                            const float* sw1, const float* sb1, const float* sw2, const float* sb2)
{
    int t = threadIdx.x;
    if (t <= NUMS) {
        float tt = t * DT;
        float a = gb2[0], b = mb2[0], c = sb2[0];
        for (int k = 0; k < KW; ++k) {
            a += tanhf(tt * gw1[k] + gb1[k]) * gw2[k];
            b += tanhf(tt * mw1[k] + mb1[k]) * mw2[k];
            c += tanhf(tt * sw1[k] + sb1[k]) * sw2[k];
        }
        d_gvals[t] = a; d_kmu[t] = b; d_ksig[t] = c;
    }
}

// ---------------- step A: assemble S_j (Volterra conv) + first-layer MLPs ----------------
// grid (16, 2): x = batch tile of 16, y = which MLP (0=mu, 1=sig). For j==128 launch (16,1), conv only.
__global__ void step_a(int j, const float* __restrict__ z0,
                       const float* __restrict__ muw1, const float* __restrict__ mub1,
                       const float* __restrict__ sgw1, const float* __restrict__ sgb1,
                       float* __restrict__ out)
{
    __shared__ float xs[16][XDIM];     // xs[r][0] = t, xs[r][1+h] = state
    __shared__ float kwv[NUMS], ksv[NUMS];
    int t  = threadIdx.x;
    int b0 = blockIdx.x * 16;

    if (t < j) { kwv[t] = DT * d_kmu[j - t]; ksv[t] = d_ksig[j - t]; }
    if (t < 16) xs[t][0] = j * DT;
    __syncthreads();

    int h  = t & 63;
    int rr = t >> 6;                   // 0..3 ; thread covers local rows rr, rr+4, rr+8, rr+12
    float acc[4] = {0.f, 0.f, 0.f, 0.f};
    for (int m = 0; m < j; ++m) {
        float km = kwv[m], ks = ksv[m];
        int base = m * (BATCH * HCH) + b0 * HCH + h;
        #pragma unroll
        for (int q = 0; q < 4; ++q) {
            int lr = rr + 4 * q;
            acc[q] += km * d_muh[base + lr * HCH] + ks * d_svh[base + lr * HCH];
        }
    }
    float gv = d_gvals[j];
    #pragma unroll
    for (int q = 0; q < 4; ++q) {
        int lr = rr + 4 * q;
        float z = z0[(b0 + lr) * HCH + h];
        float S = z * gv + acc[q];                 // output row j (for j==0 this is z*g0)
        float state = (j == 0) ? z : S;            // recursion state at j==0 is raw z0
        xs[lr][1 + h] = state;
        if (blockIdx.y == 0)
            out[(size_t)j * (BATCH * HCH) + (b0 + lr) * HCH + h] = S;
    }
    __syncthreads();

    if (j < NUMS) {
        const float* w1 = blockIdx.y ? sgw1 : muw1;
        const float* b1 = blockIdx.y ? sgb1 : mub1;
        int c = t;                                  // output hidden column 0..255
        float a2[16];
        float bias = b1[c];
        #pragma unroll
        for (int r = 0; r < 16; ++r) a2[r] = bias;
        for (int i = 0; i < XDIM; ++i) {
            float w = w1[i * HID + c];
            #pragma unroll
            for (int r = 0; r < 16; ++r) a2[r] += xs[r][i] * w;
        }
        int hofs = blockIdx.y * HID;
        #pragma unroll
        for (int r = 0; r < 16; ++r)
            d_H[(b0 + r) * (2 * HID) + hofs + c] = tanhf(a2[r]);
    }
}

// ---------------- step B: second-layer GEMMs + fused dB contraction ----------------
// grid (33, 4): x = column tile (0..31 sig: 64 cols each; 32 = mu 64 cols), y = batch tile of 64.
// Tile 64x64, K=256, f32x2 packed FMA inner loop.
__global__ void step_b(int j, const float* __restrict__ Bin,
                       const float* __restrict__ muw2, const float* __restrict__ mub2,
                       const float* __restrict__ sgw2, const float* __restrict__ sgb2)
{
    __shared__ float Hs[64][33];
    __shared__ __align__(16) float Ws[32][68];
    __shared__ float dBs[64][32];
    __shared__ float sps[64][16];

    int t  = threadIdx.x;
    int cb = blockIdx.x;
    bool is_mu = (cb == 32);
    int b0 = blockIdx.y * 64;
    const float* W = is_mu ? muw2 : sgw2;
    int ldw  = is_mu ? HCH : HCH * DIM;
    int col0 = is_mu ? 0 : cb * 64;
    int hofs = is_mu ? 0 : HID;

    if (!is_mu) {
        int r = t >> 2, c = (t & 3) * 8;
        size_t rb = (size_t)(b0 + r) * (NUMS + 1) * DIM;
        #pragma unroll
        for (int q = 0; q < 8; ++q) {
            float v = Bin[rb + (size_t)(j + 1) * DIM + c + q];
            if (j > 0) v -= Bin[rb + (size_t)j * DIM + c + q];   // j==0: reference uses B[:,1,:]
            dBs[r][c + q] = v;
        }
    }

    int tx = t & 15, ty = t >> 4;
    int r0 = ty * 4, c0 = tx * 4;
    unsigned long long acc2[4][2];
    #pragma unroll
    for (int i = 0; i < 4; ++i) { acc2[i][0] = 0ull; acc2[i][1] = 0ull; }

    for (int kc = 0; kc < 8; ++kc) {
        __syncthreads();
        {   // load H tile [64 x 32]
            int r = t >> 2, c = (t & 3) * 8;
            const float* src = &d_H[(b0 + r) * (2 * HID) + hofs + kc * 32 + c];
            float4 v0 = *reinterpret_cast<const float4*>(src);
            float4 v1 = *reinterpret_cast<const float4*>(src + 4);
            Hs[r][c + 0] = v0.x; Hs[r][c + 1] = v0.y; Hs[r][c + 2] = v0.z; Hs[r][c + 3] = v0.w;
            Hs[r][c + 4] = v1.x; Hs[r][c + 5] = v1.y; Hs[r][c + 6] = v1.z; Hs[r][c + 7] = v1.w;
        }
        {   // load W tile [32 x 64]
            int kr = t >> 3, c = (t & 7) * 8;
            const float* src = &W[(size_t)(kc * 32 + kr) * ldw + col0 + c];
            float4 v0 = *reinterpret_cast<const float4*>(src);
            float4 v1 = *reinterpret_cast<const float4*>(src + 4);
            Ws[kr][c + 0] = v0.x; Ws[kr][c + 1] = v0.y; Ws[kr][c + 2] = v0.z; Ws[kr][c + 3] = v0.w;
            Ws[kr][c + 4] = v1.x; Ws[kr][c + 5] = v1.y; Ws[kr][c + 6] = v1.z; Ws[kr][c + 7] = v1.w;
        }
        __syncthreads();
        #pragma unroll
        for (int kk = 0; kk < 32; ++kk) {
            const unsigned long long* wp =
                reinterpret_cast<const unsigned long long*>(&Ws[kk][c0]);
            unsigned long long bl = wp[0], bh = wp[1];
            #pragma unroll
            for (int i = 0; i < 4; ++i) {
                float a = Hs[r0 + i][kk];
                unsigned long long a2;
                asm("mov.b64 %0, {%1, %1};" : "=l"(a2) : "f"(a));
                asm("fma.rn.f32x2 %0, %1, %2, %3;"
                    : "=l"(acc2[i][0]) : "l"(a2), "l"(bl), "l"(acc2[i][0]));
                asm("fma.rn.f32x2 %0, %1, %2, %3;"
                    : "=l"(acc2[i][1]) : "l"(a2), "l"(bh), "l"(acc2[i][1]));
            }
        }
    }

    float C[4][4];
    #pragma unroll
    for (int i = 0; i < 4; ++i) {
        asm("mov.b64 {%0, %1}, %2;" : "=f"(C[i][0]), "=f"(C[i][1]) : "l"(acc2[i][0]));
        asm("mov.b64 {%0, %1}, %2;" : "=f"(C[i][2]), "=f"(C[i][3]) : "l"(acc2[i][1]));
    }

    if (is_mu) {
        #pragma unroll
        for (int i = 0; i < 4; ++i)
            #pragma unroll
            for (int jj = 0; jj < 4; ++jj)
                d_muh[(size_t)j * (BATCH * HCH) + (b0 + r0 + i) * HCH + c0 + jj]
                    = C[i][jj] + mub2[c0 + jj];
    } else {
        // fused d-contraction: this block's 64 cols cover h = 2*cb, 2*cb+1
        int dof = c0 & 31;
        float p[4];
        #pragma unroll
        for (int i = 0; i < 4; ++i) {
            float s = 0.f;
            #pragma unroll
            for (int jj = 0; jj < 4; ++jj)
                s += (C[i][jj] + sgb2[col0 + c0 + jj]) * dBs[r0 + i][dof + jj];
            p[i] = s;
        }
        #pragma unroll
        for (int i = 0; i < 4; ++i) sps[r0 + i][tx] = p[i];
        __syncthreads();
        if (t < 128) {
            int r = t >> 1, hh = t & 1;
            float s = 0.f;
            #pragma unroll
            for (int g = 0; g < 8; ++g) s += sps[r][hh * 8 + g];
            d_svh[(size_t)j * (BATCH * HCH) + (b0 + r) * HCH + cb * 2 + hh] = s;
        }
    }
}

// ---------------- launch ----------------
extern "C" void kernel_launch(void* const* d_in, const int* in_sizes, int n_in,
                              void* d_out, int out_size)
{
    const float* B    = (const float*)d_in[0];
    const float* z0   = (const float*)d_in[1];
    const float* gw1  = (const float*)d_in[6];
    const float* gb1  = (const float*)d_in[7];
    const float* gw2  = (const float*)d_in[8];
    const float* gb2  = (const float*)d_in[9];
    const float* kmw1 = (const float*)d_in[10];
    const float* kmb1 = (const float*)d_in[11];
    const float* kmw2 = (const float*)d_in[12];
    const float* kmb2 = (const float*)d_in[13];
    const float* ksw1 = (const float*)d_in[14];
    const float* ksb1 = (const float*)d_in[15];
    const float* ksw2 = (const float*)d_in[16];
    const float* ksb2 = (const float*)d_in[17];
    const float* muw1 = (const float*)d_in[18];
    const float* mub1 = (const float*)d_in[19];
    const float* muw2 = (const float*)d_in[20];
    const float* mub2 = (const float*)d_in[21];
    const float* sgw1 = (const float*)d_in[22];
    const float* sgb1 = (const float*)d_in[23];
    const float* sgw2 = (const float*)d_in[24];
    const float* sgb2 = (const float*)d_in[25];
    float* out = (float*)d_out;

    init_kernel<<<1, 256>>>(gw1, gb1, gw2, gb2, kmw1, kmb1, kmw2, kmb2,
                            ksw1, ksb1, ksw2, ksb2);
    for (int j = 0; j < NUMS; ++j) {
        step_a<<<dim3(16, 2), 256>>>(j, z0, muw1, mub1, sgw1, sgb1, out);
        step_b<<<dim3(33, 4), 256>>>(j, B, muw2, mub2, sgw2, sgb2);
    }
    step_a<<<dim3(16, 1), 256>>>(NUMS, z0, muw1, mub1, sgw1, sgb1, out);
}